// round 13
// baseline (speedup 1.0000x reference)
#include <cuda_runtime.h>
#include <cuda_bf16.h>
#include <cstdint>

#define N_TREES     15
#define DEPTH       3
#define INPUT_DIM   128
#define N_CLASSES   10
#define N_LEAVES    8
#define N_INTERNAL  7
#define PER_TREE    983          // 7*128 + 7 + 8*10
#define NODES       105
#define N_PAD       112          // 14 * 8
#define TILE_M      128
#define THREADS     256          // 8 warps: 4 M-groups(M=32) x 2 N-halves(N=56)
#define M_STRIDE    12           // padded leaf-class row (10 -> 12 for float4)

// ---- smem byte offsets ----
#define OFF_MTAB    0            // 15*8*12 floats = 5760 B
#define OFF_BIAS    5760         // 112 floats = 448 B
#define OFF_BHI     6272         // 112x128 bf16 swizzled = 28672 B
#define OFF_AHI     34944        // 128x128 bf16 swizzled = 32768 B
#define OFF_ALO     67712        // 32768 B (A_lo; reused for B_lo in pass 2)
#define SMEM_TOTAL  100480
// overlays after mainloop:
#define OFF_ZS      OFF_AHI      // z tile 128*116*4 = 59392 B
#define OFF_OSM     OFF_BHI      // 2*128*10 floats = 10240 B (B_hi dead)
#define Z_STRIDE    116          // 464 B/row: 16B-aligned rows

#define B_BYTES     28672        // 112 rows * 256 B

typedef unsigned long long ull;

__device__ __align__(16) unsigned char gBhi[B_BYTES];
__device__ __align__(16) unsigned char gBlo[B_BYTES];
__device__ float gBias[N_PAD];
__device__ __align__(16) float gMtab[N_TREES * N_LEAVES * M_STRIDE];

#define MMA16816(cc, a0, a1, a2, a3, b0, b1) \
    asm volatile("mma.sync.aligned.m16n8k16.row.col.f32.bf16.bf16.f32 " \
        "{%0,%1,%2,%3}, {%4,%5,%6,%7}, {%8,%9}, {%0,%1,%2,%3};" \
        : "+f"((cc)[0]), "+f"((cc)[1]), "+f"((cc)[2]), "+f"((cc)[3]) \
        : "r"(a0), "r"(a1), "r"(a2), "r"(a3), "r"(b0), "r"(b1))

#define LDSM_X4(r0, r1, r2, r3, addr) \
    asm volatile("ldmatrix.sync.aligned.m8n8.x4.shared.b16 {%0,%1,%2,%3}, [%4];" \
        : "=r"(r0), "=r"(r1), "=r"(r2), "=r"(r3) : "r"(addr))

#define LDSM_X2(r0, r1, addr) \
    asm volatile("ldmatrix.sync.aligned.m8n8.x2.shared.b16 {%0,%1}, [%2];" \
        : "=r"(r0), "=r"(r1) : "r"(addr))

#define FMA2(acc, a, b) \
    asm("fma.rn.f32x2 %0, %1, %2, %0;" : "+l"(acc) : "l"(a), "l"(b))

__device__ __forceinline__ ull pack2(float lo, float hi) {
    ull r; asm("mov.b64 %0, {%1, %2};" : "=l"(r) : "f"(lo), "f"(hi)); return r;
}

// packed fp32 pair -> bf16x2 (hi/lo split); rn rounding identical to __float2bfloat16
__device__ __forceinline__ void cvt_split(float a, float b, uint32_t& hh, uint32_t& ll) {
    uint32_t h;
    asm("cvt.rn.bf16x2.f32 %0, %1, %2;" : "=r"(h) : "f"(b), "f"(a));  // lo=a, hi=b
    float fa = __uint_as_float(h << 16);
    float fb = __uint_as_float(h & 0xffff0000u);
    float la = a - fa;
    float lb = b - fb;
    uint32_t l;
    asm("cvt.rn.bf16x2.f32 %0, %1, %2;" : "=r"(l) : "f"(lb), "f"(la));
    hh = h; ll = l;
}

// swizzled byte offset inside a [rows][128 bf16] tile
__device__ __host__ __forceinline__ uint32_t swz(int row, int chunk, int inb) {
    return (uint32_t)(row * 256 + (((chunk) ^ (row & 7)) << 4) + inb);
}

__device__ __forceinline__ uint32_t smem_u32(const void* p) {
    uint32_t a;
    asm("{ .reg .u64 t; cvta.to.shared.u64 t, %1; cvt.u32.u64 %0, t; }"
        : "=r"(a) : "l"(p));
    return a;
}

// ===================== setup kernel: convert W once =====================
__global__ void sdt_setup_kernel(const float* __restrict__ params)
{
    const int tid = threadIdx.x;   // 128 threads

    for (int idx = tid; idx < N_PAD * INPUT_DIM; idx += 128) {
        int row = idx >> 7;
        int col = idx & 127;
        float v = 0.f;
        if (row < NODES) {
            int t = row / N_INTERNAL;
            int n = row - t * N_INTERNAL;
            v = params[t * PER_TREE + n * INPUT_DIM + col];
        }
        __nv_bfloat16 h = __float2bfloat16(v);
        __nv_bfloat16 l = __float2bfloat16(v - __bfloat162float(h));
        uint32_t o = swz(row, col >> 3, (col & 7) << 1);
        *reinterpret_cast<__nv_bfloat16*>(gBhi + o) = h;
        *reinterpret_cast<__nv_bfloat16*>(gBlo + o) = l;
    }
    if (tid < N_PAD) {
        float v = 0.f;
        if (tid < NODES) {
            int t = tid / N_INTERNAL;
            int n = tid - t * N_INTERNAL;
            v = params[t * PER_TREE + N_INTERNAL * INPUT_DIM + n];
        }
        gBias[tid] = v;
    }
    if (tid < N_TREES * N_LEAVES) {
        int t = tid / N_LEAVES;
        int l = tid - t * N_LEAVES;
        const float* twl = params + N_TREES * PER_TREE;
        float mx = twl[0];
        #pragma unroll
        for (int i = 1; i < N_TREES; ++i) mx = fmaxf(mx, twl[i]);
        float s = 0.f;
        #pragma unroll
        for (int i = 0; i < N_TREES; ++i) s += __expf(twl[i] - mx);
        float tw = __expf(twl[t] - mx) / s;

        const float* ll = params + t * PER_TREE + N_INTERNAL * INPUT_DIM + N_INTERNAL
                        + l * N_CLASSES;
        float m2 = ll[0];
        #pragma unroll
        for (int c = 1; c < N_CLASSES; ++c) m2 = fmaxf(m2, ll[c]);
        float e[N_CLASSES];
        float s2 = 0.f;
        #pragma unroll
        for (int c = 0; c < N_CLASSES; ++c) { e[c] = __expf(ll[c] - m2); s2 += e[c]; }
        float inv = tw / s2;
        #pragma unroll
        for (int c = 0; c < N_CLASSES; ++c)
            gMtab[(t * N_LEAVES + l) * M_STRIDE + c] = e[c] * inv;
        gMtab[(t * N_LEAVES + l) * M_STRIDE + 10] = 0.f;
        gMtab[(t * N_LEAVES + l) * M_STRIDE + 11] = 0.f;
    }
}

// ---- tree epilogue over NT trees for one row; z/bias/M pre-offset ----
template<int NT>
__device__ __forceinline__ void tree_epi2(const float* __restrict__ zv,
                                          const float* __restrict__ bias,
                                          const float* __restrict__ Msm0,
                                          ull* __restrict__ acc2)
{
    #pragma unroll
    for (int k = 0; k < 5; ++k) acc2[k] = 0ull;

    #pragma unroll
    for (int t = 0; t < NT; ++t) {
        float p_[N_INTERNAL], q_[N_INTERNAL];
        #pragma unroll
        for (int n = 0; n < N_INTERNAL; ++n) {
            float zz = zv[t * N_INTERNAL + n] + bias[t * N_INTERNAL + n];
            float e  = __expf(-zz);
            float pp = 1.f / (1.f + e);   // sigmoid(z)  -> right
            p_[n] = pp;
            q_[n] = e * pp;               // sigmoid(-z) -> left
        }
        float tp[N_LEAVES];
        #pragma unroll
        for (int l = 0; l < N_LEAVES; ++l) {
            int node = l + N_INTERNAL;
            float prob = 1.f;
            #pragma unroll
            for (int d = 0; d < DEPTH; ++d) {
                int par = (node - 1) >> 1;
                prob *= (node & 1) ? q_[par] : p_[par];
                node = par;
            }
            tp[l] = prob;
        }
        #pragma unroll
        for (int l = 0; l < N_LEAVES; ++l) {
            const ulonglong2* Mv = reinterpret_cast<const ulonglong2*>(
                Msm0 + (t * N_LEAVES + l) * M_STRIDE);
            ulonglong2 m01 = Mv[0];   // classes 0-3
            ulonglong2 m23 = Mv[1];   // classes 4-7
            ull m4 = *reinterpret_cast<const ull*>(
                Msm0 + (t * N_LEAVES + l) * M_STRIDE + 8);  // classes 8-9
            ull ww = pack2(tp[l], tp[l]);
            FMA2(acc2[0], ww, m01.x);
            FMA2(acc2[1], ww, m01.y);
            FMA2(acc2[2], ww, m23.x);
            FMA2(acc2[3], ww, m23.y);
            FMA2(acc2[4], ww, m4);
        }
    }
}

// ===================== main kernel =====================
__global__ __launch_bounds__(THREADS, 2)
void sdt_mma_kernel(const float* __restrict__ x,
                    float* __restrict__ out,
                    int batch)
{
    extern __shared__ char smem[];
    const uint32_t sb = smem_u32(smem);
    const int tid  = threadIdx.x;
    const int lane = tid & 31;
    const int w    = tid >> 5;         // 0..7
    const int mgrp = w >> 1;           // 0..3: rows mgrp*32 .. +31
    const int nh   = w & 1;            // 0/1:  cols nh*56 .. +55

    // ---- copy precomputed B_hi, Mtab, bias into smem ----
    {
        const uint4* src = reinterpret_cast<const uint4*>(gBhi);
        uint4* dst = reinterpret_cast<uint4*>(smem + OFF_BHI);
        #pragma unroll
        for (int i = 0; i < B_BYTES / 16 / THREADS; ++i)
            dst[tid + i * THREADS] = src[tid + i * THREADS];

        float* msm = reinterpret_cast<float*>(smem + OFF_MTAB);
        for (int i = tid; i < N_TREES * N_LEAVES * M_STRIDE; i += THREADS)
            msm[i] = gMtab[i];
        float* bsm = reinterpret_cast<float*>(smem + OFF_BIAS);
        if (tid < N_PAD) bsm[tid] = gBias[tid];
    }

    // ---- stage A: x tile -> bf16 hi/lo, swizzled (packed cvt, 8B stores) ----
    {
        const float4* xv = reinterpret_cast<const float4*>(x)
                         + (size_t)blockIdx.x * TILE_M * (INPUT_DIM / 4);
        #pragma unroll
        for (int it = 0; it < TILE_M * (INPUT_DIM / 4) / THREADS; ++it) {
            int idx = tid + it * THREADS;
            int r  = idx >> 5;
            int c4 = idx & 31;
            float4 v = xv[idx];
            uint32_t h01, l01, h23, l23;
            cvt_split(v.x, v.y, h01, l01);
            cvt_split(v.z, v.w, h23, l23);
            uint32_t base = swz(r, c4 >> 1, (c4 & 1) << 3);   // 8B aligned
            uint2 hh = make_uint2(h01, h23);
            uint2 llv = make_uint2(l01, l23);
            *reinterpret_cast<uint2*>(smem + OFF_AHI + base) = hh;
            *reinterpret_cast<uint2*>(smem + OFF_ALO + base) = llv;
        }
    }
    __syncthreads();

    // ================= bf16-split HMMA mainloop =================
    // fused loop: per ks load Ah+Al+all B_hi frags; 14 Ah-MMAs then 14 Al-MMAs
    //             (same-cc distance = 14; B frags loaded once for both)
    // loop 2:    Ah vs B_lo (B_lo copied into dead A_lo region)
    const int arow_in16 = ((lane >> 3) & 1) * 8 + (lane & 7);
    const int apar      = lane >> 4;
    const int nbase      = nh * 56;
    const int brow_local = ((lane >> 4) & 1) * 8 + (lane & 7);
    const int bpar       = (lane >> 3) & 1;
    const int brow2      = nbase + 48 + (lane & 7);
    const int bpar2      = (lane >> 3) & 1;

    float cc[2][7][4];
    #pragma unroll
    for (int mt = 0; mt < 2; ++mt)
        #pragma unroll
        for (int nt = 0; nt < 7; ++nt)
            #pragma unroll
            for (int i = 0; i < 4; ++i) cc[mt][nt][i] = 0.f;

    const uint32_t sBHI = sb + OFF_BHI;
    const uint32_t sAHI = sb + OFF_AHI;
    const uint32_t sALO = sb + OFF_ALO;

    // ---- fused loop: (Ah then Al) vs B_hi, B frags shared ----
    #pragma unroll
    for (int ks = 0; ks < 8; ++ks) {
        const int ch  = ks * 2;
        const int ach = ch + apar;
        uint32_t ah[2][4], al[2][4];
        #pragma unroll
        for (int mt = 0; mt < 2; ++mt) {
            int arow = mgrp * 32 + mt * 16 + arow_in16;
            uint32_t aoff = (uint32_t)arow * 256 + ((ach ^ (arow & 7)) << 4);
            LDSM_X4(ah[mt][0], ah[mt][1], ah[mt][2], ah[mt][3], sAHI + aoff);
            LDSM_X4(al[mt][0], al[mt][1], al[mt][2], al[mt][3], sALO + aoff);
        }
        // load ALL B_hi frags for this ks (kept live: 14 regs)
        uint32_t bf[3][4];
        uint32_t b2a, b2b;
        #pragma unroll
        for (int j = 0; j < 3; ++j) {
            int brow = nbase + j * 16 + brow_local;
            int bch  = ch + bpar;
            LDSM_X4(bf[j][0], bf[j][1], bf[j][2], bf[j][3],
                    sBHI + brow * 256 + ((bch ^ (brow & 7)) << 4));
        }
        {
            int bch = ch + bpar2;
            LDSM_X2(b2a, b2b, sBHI + brow2 * 256 + ((bch ^ (brow2 & 7)) << 4));
        }
        // 14 MMAs with Ah
        #pragma unroll
        for (int j = 0; j < 3; ++j) {
            MMA16816(cc[0][2 * j],     ah[0][0], ah[0][1], ah[0][2], ah[0][3], bf[j][0], bf[j][1]);
            MMA16816(cc[0][2 * j + 1], ah[0][0], ah[0][1], ah[0][2], ah[0][3], bf[j][2], bf[j][3]);
            MMA16816(cc[1][2 * j],     ah[1][0], ah[1][1], ah[1][2], ah[1][3], bf[j][0], bf[j][1]);
            MMA16816(cc[1][2 * j + 1], ah[1][0], ah[1][1], ah[1][2], ah[1][3], bf[j][2], bf[j][3]);
        }
        MMA16816(cc[0][6], ah[0][0], ah[0][1], ah[0][2], ah[0][3], b2a, b2b);
        MMA16816(cc[1][6], ah[1][0], ah[1][1], ah[1][2], ah[1][3], b2a, b2b);
        // 14 MMAs with Al (same cc, distance 14)
        #pragma unroll
        for (int j = 0; j < 3; ++j) {
            MMA16816(cc[0][2 * j],     al[0][0], al[0][1], al[0][2], al[0][3], bf[j][0], bf[j][1]);
            MMA16816(cc[0][2 * j + 1], al[0][0], al[0][1], al[0][2], al[0][3], bf[j][2], bf[j][3]);
            MMA16816(cc[1][2 * j],     al[1][0], al[1][1], al[1][2], al[1][3], bf[j][0], bf[j][1]);
            MMA16816(cc[1][2 * j + 1], al[1][0], al[1][1], al[1][2], al[1][3], bf[j][2], bf[j][3]);
        }
        MMA16816(cc[0][6], al[0][0], al[0][1], al[0][2], al[0][3], b2a, b2b);
        MMA16816(cc[1][6], al[1][0], al[1][1], al[1][2], al[1][3], b2a, b2b);
    }

    // ---- A_lo consumed; overwrite its region with B_lo ----
    __syncthreads();
    {
        const uint4* src = reinterpret_cast<const uint4*>(gBlo);
        uint4* dst = reinterpret_cast<uint4*>(smem + OFF_ALO);
        #pragma unroll
        for (int i = 0; i < B_BYTES / 16 / THREADS; ++i)
            dst[tid + i * THREADS] = src[tid + i * THREADS];
    }
    __syncthreads();

    // ---- loop 2: Ah vs B_lo ----
    #pragma unroll
    for (int ks = 0; ks < 8; ++ks) {
        const int ch  = ks * 2;
        const int ach = ch + apar;
        uint32_t a[2][4];
        #pragma unroll
        for (int mt = 0; mt < 2; ++mt) {
            int arow = mgrp * 32 + mt * 16 + arow_in16;
            LDSM_X4(a[mt][0], a[mt][1], a[mt][2], a[mt][3],
                    sAHI + arow * 256 + ((ach ^ (arow & 7)) << 4));
        }
        #pragma unroll
        for (int j = 0; j < 3; ++j) {
            int brow = nbase + j * 16 + brow_local;
            int bch  = ch + bpar;
            uint32_t b0A, b1A, b0B, b1B;
            LDSM_X4(b0A, b1A, b0B, b1B,
                    sALO + brow * 256 + ((bch ^ (brow & 7)) << 4));
            MMA16816(cc[0][2 * j],     a[0][0], a[0][1], a[0][2], a[0][3], b0A, b1A);
            MMA16816(cc[0][2 * j + 1], a[0][0], a[0][1], a[0][2], a[0][3], b0B, b1B);
            MMA16816(cc[1][2 * j],     a[1][0], a[1][1], a[1][2], a[1][3], b0A, b1A);
            MMA16816(cc[1][2 * j + 1], a[1][0], a[1][1], a[1][2], a[1][3], b0B, b1B);
        }
        {
            uint32_t b0, b1;
            int bch = ch + bpar2;
            LDSM_X2(b0, b1, sALO + brow2 * 256 + ((bch ^ (brow2 & 7)) << 4));
            MMA16816(cc[0][6], a[0][0], a[0][1], a[0][2], a[0][3], b0, b1);
            MMA16816(cc[1][6], a[1][0], a[1][1], a[1][2], a[1][3], b0, b1);
        }
    }

    // ---- scatter accumulators to z tile (64-bit packed stores) ----
    __syncthreads();
    float* zsm = reinterpret_cast<float*>(smem + OFF_ZS);
    {
        const int rsub  = lane >> 2;
        const int cbase = nbase + ((lane & 3) << 1);
        #pragma unroll
        for (int mt = 0; mt < 2; ++mt) {
            int row = mgrp * 32 + mt * 16 + rsub;
            #pragma unroll
            for (int nt = 0; nt < 7; ++nt) {
                int col = nt * 8 + cbase;   // even -> 8B aligned
                *reinterpret_cast<ull*>(&zsm[row * Z_STRIDE + col]) =
                    pack2(cc[mt][nt][0], cc[mt][nt][1]);
                *reinterpret_cast<ull*>(&zsm[(row + 8) * Z_STRIDE + col]) =
                    pack2(cc[mt][nt][2], cc[mt][nt][3]);
            }
        }
    }
    __syncthreads();

    // ---- tree epilogue: all 256 threads; row = tid&127, tree-half = tid>>7 ----
    {
        const float* Msm = reinterpret_cast<const float*>(smem + OFF_MTAB);
        const float* bsm = reinterpret_cast<const float*>(smem + OFF_BIAS);
        float* osm = reinterpret_cast<float*>(smem + OFF_OSM);  // [2][128][10]

        const int r    = tid & 127;
        const int half = tid >> 7;
        const float* zrow = zsm + r * Z_STRIDE;

        float zv[56];
        ull acc2[5];
        if (half == 0) {
            #pragma unroll
            for (int i = 0; i < 14; ++i) {
                float4 v = reinterpret_cast<const float4*>(zrow)[i];
                zv[4 * i + 0] = v.x; zv[4 * i + 1] = v.y;
                zv[4 * i + 2] = v.z; zv[4 * i + 3] = v.w;
            }
            tree_epi2<8>(zv, bsm, Msm, acc2);
        } else {
            #pragma unroll
            for (int i = 0; i < 12; ++i) {
                float4 v = reinterpret_cast<const float4*>(zrow + 56)[i];
                zv[4 * i + 0] = v.x; zv[4 * i + 1] = v.y;
                zv[4 * i + 2] = v.z; zv[4 * i + 3] = v.w;
            }
            zv[48] = zrow[104];
            tree_epi2<7>(zv, bsm + 56, Msm + 8 * N_LEAVES * M_STRIDE, acc2);
        }

        ull* od = reinterpret_cast<ull*>(osm + (half * TILE_M + r) * N_CLASSES);
        #pragma unroll
        for (int k = 0; k < 5; ++k) od[k] = acc2[k];
    }
    __syncthreads();

    // ---- sum halves, then coalesced store ----
    {
        float* osm = reinterpret_cast<float*>(smem + OFF_OSM);
        if (tid < TILE_M) {
            #pragma unroll
            for (int c = 0; c < N_CLASSES; ++c)
                osm[tid * N_CLASSES + c] += osm[(TILE_M + tid) * N_CLASSES + c];
        }
        __syncthreads();
        const uint4* osv = reinterpret_cast<const uint4*>(osm);
        uint4* og = reinterpret_cast<uint4*>(out + (size_t)blockIdx.x * TILE_M * N_CLASSES);
        #pragma unroll
        for (int i = tid; i < TILE_M * N_CLASSES / 4; i += THREADS)
            og[i] = osv[i];
    }
}

extern "C" void kernel_launch(void* const* d_in, const int* in_sizes, int n_in,
                              void* d_out, int out_size)
{
    const float* x      = (const float*)d_in[0];
    const float* params = (const float*)d_in[1];
    float* out          = (float*)d_out;

    int batch = in_sizes[0] / INPUT_DIM;

    cudaFuncSetAttribute(sdt_mma_kernel,
                         cudaFuncAttributeMaxDynamicSharedMemorySize,
                         SMEM_TOTAL);

    sdt_setup_kernel<<<1, 128>>>(params);

    int grid = (batch + TILE_M - 1) / TILE_M;
    sdt_mma_kernel<<<grid, THREADS, SMEM_TOTAL>>>(x, out, batch);
}

// round 14
// speedup vs baseline: 1.1401x; 1.1401x over previous
#include <cuda_runtime.h>
#include <cuda_bf16.h>
#include <cstdint>

#define N_TREES     15
#define DEPTH       3
#define INPUT_DIM   128
#define N_CLASSES   10
#define N_LEAVES    8
#define N_INTERNAL  7
#define PER_TREE    983          // 7*128 + 7 + 8*10
#define NODES       105
#define N_PAD       112          // 14 * 8
#define TILE_M      128
#define THREADS     256          // 8 warps: 4 M-groups(M=32) x 2 N-halves(N=56)
#define M_STRIDE    12           // padded leaf-class row (10 -> 12 for float4)

// ---- smem byte offsets ----
#define OFF_MTAB    0            // 15*8*12 floats = 5760 B
#define OFF_BIAS    5760         // 112 floats = 448 B
#define OFF_BHI     6272         // 112x128 bf16 swizzled = 28672 B
#define OFF_AHI     34944        // 128x128 bf16 swizzled = 32768 B
#define OFF_ALO     67712        // 32768 B (A_lo; reused for B_lo in pass 2)
#define SMEM_TOTAL  100480
// overlays after mainloop:
#define OFF_ZS      OFF_AHI      // z tile 128*116*4 = 59392 B
#define OFF_OSM     OFF_BHI      // 2*128*10 floats = 10240 B (B_hi dead)
#define Z_STRIDE    116          // 464 B/row: 16B-aligned rows

#define B_BYTES     28672        // 112 rows * 256 B
#define SETUP_BLOCKS 64

typedef unsigned long long ull;

__device__ __align__(16) unsigned char gBhi[B_BYTES];
__device__ __align__(16) unsigned char gBlo[B_BYTES];
__device__ float gBias[N_PAD];
__device__ __align__(16) float gMtab[N_TREES * N_LEAVES * M_STRIDE];

#define MMA16816(cc, a0, a1, a2, a3, b0, b1) \
    asm volatile("mma.sync.aligned.m16n8k16.row.col.f32.bf16.bf16.f32 " \
        "{%0,%1,%2,%3}, {%4,%5,%6,%7}, {%8,%9}, {%0,%1,%2,%3};" \
        : "+f"((cc)[0]), "+f"((cc)[1]), "+f"((cc)[2]), "+f"((cc)[3]) \
        : "r"(a0), "r"(a1), "r"(a2), "r"(a3), "r"(b0), "r"(b1))

#define LDSM_X4(r0, r1, r2, r3, addr) \
    asm volatile("ldmatrix.sync.aligned.m8n8.x4.shared.b16 {%0,%1,%2,%3}, [%4];" \
        : "=r"(r0), "=r"(r1), "=r"(r2), "=r"(r3) : "r"(addr))

#define LDSM_X2(r0, r1, addr) \
    asm volatile("ldmatrix.sync.aligned.m8n8.x2.shared.b16 {%0,%1}, [%2];" \
        : "=r"(r0), "=r"(r1) : "r"(addr))

#define FMA2(acc, a, b) \
    asm("fma.rn.f32x2 %0, %1, %2, %0;" : "+l"(acc) : "l"(a), "l"(b))

__device__ __forceinline__ ull pack2(float lo, float hi) {
    ull r; asm("mov.b64 %0, {%1, %2};" : "=l"(r) : "f"(lo), "f"(hi)); return r;
}

// packed fp32 pair -> bf16x2 (hi/lo split); rn rounding identical to __float2bfloat16
__device__ __forceinline__ void cvt_split(float a, float b, uint32_t& hh, uint32_t& ll) {
    uint32_t h;
    asm("cvt.rn.bf16x2.f32 %0, %1, %2;" : "=r"(h) : "f"(b), "f"(a));  // lo=a, hi=b
    float fa = __uint_as_float(h << 16);
    float fb = __uint_as_float(h & 0xffff0000u);
    float la = a - fa;
    float lb = b - fb;
    uint32_t l;
    asm("cvt.rn.bf16x2.f32 %0, %1, %2;" : "=r"(l) : "f"(lb), "f"(la));
    hh = h; ll = l;
}

// swizzled byte offset inside a [rows][128 bf16] tile
__device__ __host__ __forceinline__ uint32_t swz(int row, int chunk, int inb) {
    return (uint32_t)(row * 256 + (((chunk) ^ (row & 7)) << 4) + inb);
}

__device__ __forceinline__ uint32_t smem_u32(const void* p) {
    uint32_t a;
    asm("{ .reg .u64 t; cvta.to.shared.u64 t, %1; cvt.u32.u64 %0, t; }"
        : "=r"(a) : "l"(p));
    return a;
}

// ===================== setup kernel: convert W once (parallel grid) =====================
__global__ void sdt_setup_kernel(const float* __restrict__ params)
{
    const int tid = threadIdx.x;
    const int gidx = blockIdx.x * blockDim.x + tid;
    const int gstride = gridDim.x * blockDim.x;

    // weight conversion: grid-strided over all blocks
    for (int idx = gidx; idx < N_PAD * INPUT_DIM; idx += gstride) {
        int row = idx >> 7;
        int col = idx & 127;
        float v = 0.f;
        if (row < NODES) {
            int t = row / N_INTERNAL;
            int n = row - t * N_INTERNAL;
            v = params[t * PER_TREE + n * INPUT_DIM + col];
        }
        __nv_bfloat16 h = __float2bfloat16(v);
        __nv_bfloat16 l = __float2bfloat16(v - __bfloat162float(h));
        uint32_t o = swz(row, col >> 3, (col & 7) << 1);
        *reinterpret_cast<__nv_bfloat16*>(gBhi + o) = h;
        *reinterpret_cast<__nv_bfloat16*>(gBlo + o) = l;
    }

    // bias + Mtab: block 0 only
    if (blockIdx.x == 0) {
        if (tid < N_PAD) {
            float v = 0.f;
            if (tid < NODES) {
                int t = tid / N_INTERNAL;
                int n = tid - t * N_INTERNAL;
                v = params[t * PER_TREE + N_INTERNAL * INPUT_DIM + n];
            }
            gBias[tid] = v;
        }
        if (tid < N_TREES * N_LEAVES) {
            int t = tid / N_LEAVES;
            int l = tid - t * N_LEAVES;
            const float* twl = params + N_TREES * PER_TREE;
            float mx = twl[0];
            #pragma unroll
            for (int i = 1; i < N_TREES; ++i) mx = fmaxf(mx, twl[i]);
            float s = 0.f;
            #pragma unroll
            for (int i = 0; i < N_TREES; ++i) s += __expf(twl[i] - mx);
            float tw = __expf(twl[t] - mx) / s;

            const float* ll = params + t * PER_TREE + N_INTERNAL * INPUT_DIM + N_INTERNAL
                            + l * N_CLASSES;
            float m2 = ll[0];
            #pragma unroll
            for (int c = 1; c < N_CLASSES; ++c) m2 = fmaxf(m2, ll[c]);
            float e[N_CLASSES];
            float s2 = 0.f;
            #pragma unroll
            for (int c = 0; c < N_CLASSES; ++c) { e[c] = __expf(ll[c] - m2); s2 += e[c]; }
            float inv = tw / s2;
            #pragma unroll
            for (int c = 0; c < N_CLASSES; ++c)
                gMtab[(t * N_LEAVES + l) * M_STRIDE + c] = e[c] * inv;
            gMtab[(t * N_LEAVES + l) * M_STRIDE + 10] = 0.f;
            gMtab[(t * N_LEAVES + l) * M_STRIDE + 11] = 0.f;
        }
    }
}

// ---- tree epilogue over NT trees for one row; z/bias/M pre-offset ----
template<int NT>
__device__ __forceinline__ void tree_epi2(const float* __restrict__ zv,
                                          const float* __restrict__ bias,
                                          const float* __restrict__ Msm0,
                                          ull* __restrict__ acc2)
{
    #pragma unroll
    for (int k = 0; k < 5; ++k) acc2[k] = 0ull;

    #pragma unroll
    for (int t = 0; t < NT; ++t) {
        float p_[N_INTERNAL], q_[N_INTERNAL];
        #pragma unroll
        for (int n = 0; n < N_INTERNAL; ++n) {
            float zz = zv[t * N_INTERNAL + n] + bias[t * N_INTERNAL + n];
            float e  = __expf(-zz);
            float pp = 1.f / (1.f + e);   // sigmoid(z)  -> right
            p_[n] = pp;
            q_[n] = e * pp;               // sigmoid(-z) -> left
        }
        float tp[N_LEAVES];
        #pragma unroll
        for (int l = 0; l < N_LEAVES; ++l) {
            int node = l + N_INTERNAL;
            float prob = 1.f;
            #pragma unroll
            for (int d = 0; d < DEPTH; ++d) {
                int par = (node - 1) >> 1;
                prob *= (node & 1) ? q_[par] : p_[par];
                node = par;
            }
            tp[l] = prob;
        }
        #pragma unroll
        for (int l = 0; l < N_LEAVES; ++l) {
            const ulonglong2* Mv = reinterpret_cast<const ulonglong2*>(
                Msm0 + (t * N_LEAVES + l) * M_STRIDE);
            ulonglong2 m01 = Mv[0];   // classes 0-3
            ulonglong2 m23 = Mv[1];   // classes 4-7
            ull m4 = *reinterpret_cast<const ull*>(
                Msm0 + (t * N_LEAVES + l) * M_STRIDE + 8);  // classes 8-9
            ull ww = pack2(tp[l], tp[l]);
            FMA2(acc2[0], ww, m01.x);
            FMA2(acc2[1], ww, m01.y);
            FMA2(acc2[2], ww, m23.x);
            FMA2(acc2[3], ww, m23.y);
            FMA2(acc2[4], ww, m4);
        }
    }
}

// ===================== main kernel =====================
__global__ __launch_bounds__(THREADS, 2)
void sdt_mma_kernel(const float* __restrict__ x,
                    float* __restrict__ out,
                    int batch)
{
    extern __shared__ char smem[];
    const uint32_t sb = smem_u32(smem);
    const int tid  = threadIdx.x;
    const int lane = tid & 31;
    const int w    = tid >> 5;         // 0..7
    const int mgrp = w >> 1;           // 0..3: rows mgrp*32 .. +31
    const int nh   = w & 1;            // 0/1:  cols nh*56 .. +55

    // ---- copy precomputed B_hi, Mtab, bias into smem ----
    {
        const uint4* src = reinterpret_cast<const uint4*>(gBhi);
        uint4* dst = reinterpret_cast<uint4*>(smem + OFF_BHI);
        #pragma unroll
        for (int i = 0; i < B_BYTES / 16 / THREADS; ++i)
            dst[tid + i * THREADS] = src[tid + i * THREADS];

        float* msm = reinterpret_cast<float*>(smem + OFF_MTAB);
        for (int i = tid; i < N_TREES * N_LEAVES * M_STRIDE; i += THREADS)
            msm[i] = gMtab[i];
        float* bsm = reinterpret_cast<float*>(smem + OFF_BIAS);
        if (tid < N_PAD) bsm[tid] = gBias[tid];
    }

    // ---- stage A: x tile -> bf16 hi/lo, swizzled (packed cvt, 8B stores) ----
    {
        const float4* xv = reinterpret_cast<const float4*>(x)
                         + (size_t)blockIdx.x * TILE_M * (INPUT_DIM / 4);
        #pragma unroll
        for (int it = 0; it < TILE_M * (INPUT_DIM / 4) / THREADS; ++it) {
            int idx = tid + it * THREADS;
            int r  = idx >> 5;
            int c4 = idx & 31;
            float4 v = xv[idx];
            uint32_t h01, l01, h23, l23;
            cvt_split(v.x, v.y, h01, l01);
            cvt_split(v.z, v.w, h23, l23);
            uint32_t base = swz(r, c4 >> 1, (c4 & 1) << 3);   // 8B aligned
            uint2 hh = make_uint2(h01, h23);
            uint2 llv = make_uint2(l01, l23);
            *reinterpret_cast<uint2*>(smem + OFF_AHI + base) = hh;
            *reinterpret_cast<uint2*>(smem + OFF_ALO + base) = llv;
        }
    }
    __syncthreads();

    // ================= 3-pass bf16-split HMMA mainloop (R12 exact) =================
    const int arow_in16 = ((lane >> 3) & 1) * 8 + (lane & 7);
    const int apar      = lane >> 4;
    const int nbase      = nh * 56;
    const int brow_local = ((lane >> 4) & 1) * 8 + (lane & 7);
    const int bpar       = (lane >> 3) & 1;
    const int brow2      = nbase + 48 + (lane & 7);
    const int bpar2      = (lane >> 3) & 1;

    float cc[2][7][4];
    #pragma unroll
    for (int mt = 0; mt < 2; ++mt)
        #pragma unroll
        for (int nt = 0; nt < 7; ++nt)
            #pragma unroll
            for (int i = 0; i < 4; ++i) cc[mt][nt][i] = 0.f;

    const uint32_t sBHI = sb + OFF_BHI;
    const uint32_t sAHI = sb + OFF_AHI;
    const uint32_t sALO = sb + OFF_ALO;

    #pragma unroll 1
    for (int pass = 0; pass < 3; ++pass) {
        const uint32_t Ab = (pass == 1) ? sALO : sAHI;   // Ah, Al, Ah
        const uint32_t Bb = (pass == 2) ? sALO : sBHI;   // Bh, Bh, Bl(in ALO)
        #pragma unroll
        for (int ks = 0; ks < 8; ++ks) {
            const int ch  = ks * 2;
            const int ach = ch + apar;
            uint32_t a[2][4];
            #pragma unroll
            for (int mt = 0; mt < 2; ++mt) {
                int arow = mgrp * 32 + mt * 16 + arow_in16;
                LDSM_X4(a[mt][0], a[mt][1], a[mt][2], a[mt][3],
                        Ab + arow * 256 + ((ach ^ (arow & 7)) << 4));
            }
            #pragma unroll
            for (int j = 0; j < 3; ++j) {
                int brow = nbase + j * 16 + brow_local;
                int bch  = ch + bpar;
                uint32_t b0A, b1A, b0B, b1B;
                LDSM_X4(b0A, b1A, b0B, b1B,
                        Bb + brow * 256 + ((bch ^ (brow & 7)) << 4));
                MMA16816(cc[0][2 * j],     a[0][0], a[0][1], a[0][2], a[0][3], b0A, b1A);
                MMA16816(cc[0][2 * j + 1], a[0][0], a[0][1], a[0][2], a[0][3], b0B, b1B);
                MMA16816(cc[1][2 * j],     a[1][0], a[1][1], a[1][2], a[1][3], b0A, b1A);
                MMA16816(cc[1][2 * j + 1], a[1][0], a[1][1], a[1][2], a[1][3], b0B, b1B);
            }
            {
                uint32_t b0, b1;
                int bch = ch + bpar2;
                LDSM_X2(b0, b1, Bb + brow2 * 256 + ((bch ^ (brow2 & 7)) << 4));
                MMA16816(cc[0][6], a[0][0], a[0][1], a[0][2], a[0][3], b0, b1);
                MMA16816(cc[1][6], a[1][0], a[1][1], a[1][2], a[1][3], b0, b1);
            }
        }
        if (pass == 1) {
            // A_lo consumed; overwrite its region with B_lo for pass 2
            __syncthreads();
            const uint4* src = reinterpret_cast<const uint4*>(gBlo);
            uint4* dst = reinterpret_cast<uint4*>(smem + OFF_ALO);
            #pragma unroll
            for (int i = 0; i < B_BYTES / 16 / THREADS; ++i)
                dst[tid + i * THREADS] = src[tid + i * THREADS];
            __syncthreads();
        }
    }

    // ---- scatter accumulators to z tile (64-bit packed stores) ----
    __syncthreads();
    float* zsm = reinterpret_cast<float*>(smem + OFF_ZS);
    {
        const int rsub  = lane >> 2;
        const int cbase = nbase + ((lane & 3) << 1);
        #pragma unroll
        for (int mt = 0; mt < 2; ++mt) {
            int row = mgrp * 32 + mt * 16 + rsub;
            #pragma unroll
            for (int nt = 0; nt < 7; ++nt) {
                int col = nt * 8 + cbase;   // even -> 8B aligned
                *reinterpret_cast<ull*>(&zsm[row * Z_STRIDE + col]) =
                    pack2(cc[mt][nt][0], cc[mt][nt][1]);
                *reinterpret_cast<ull*>(&zsm[(row + 8) * Z_STRIDE + col]) =
                    pack2(cc[mt][nt][2], cc[mt][nt][3]);
            }
        }
    }
    __syncthreads();

    // ---- tree epilogue: all 256 threads; row = tid&127, tree-half = tid>>7 ----
    {
        const float* Msm = reinterpret_cast<const float*>(smem + OFF_MTAB);
        const float* bsm = reinterpret_cast<const float*>(smem + OFF_BIAS);
        float* osm = reinterpret_cast<float*>(smem + OFF_OSM);  // [2][128][10]

        const int r    = tid & 127;
        const int half = tid >> 7;
        const float* zrow = zsm + r * Z_STRIDE;

        float zv[56];
        ull acc2[5];
        if (half == 0) {
            #pragma unroll
            for (int i = 0; i < 14; ++i) {
                float4 v = reinterpret_cast<const float4*>(zrow)[i];
                zv[4 * i + 0] = v.x; zv[4 * i + 1] = v.y;
                zv[4 * i + 2] = v.z; zv[4 * i + 3] = v.w;
            }
            tree_epi2<8>(zv, bsm, Msm, acc2);
        } else {
            #pragma unroll
            for (int i = 0; i < 12; ++i) {
                float4 v = reinterpret_cast<const float4*>(zrow + 56)[i];
                zv[4 * i + 0] = v.x; zv[4 * i + 1] = v.y;
                zv[4 * i + 2] = v.z; zv[4 * i + 3] = v.w;
            }
            zv[48] = zrow[104];
            tree_epi2<7>(zv, bsm + 56, Msm + 8 * N_LEAVES * M_STRIDE, acc2);
        }

        ull* od = reinterpret_cast<ull*>(osm + (half * TILE_M + r) * N_CLASSES);
        #pragma unroll
        for (int k = 0; k < 5; ++k) od[k] = acc2[k];
    }
    __syncthreads();

    // ---- sum halves, then coalesced store ----
    {
        float* osm = reinterpret_cast<float*>(smem + OFF_OSM);
        if (tid < TILE_M) {
            #pragma unroll
            for (int c = 0; c < N_CLASSES; ++c)
                osm[tid * N_CLASSES + c] += osm[(TILE_M + tid) * N_CLASSES + c];
        }
        __syncthreads();
        const uint4* osv = reinterpret_cast<const uint4*>(osm);
        uint4* og = reinterpret_cast<uint4*>(out + (size_t)blockIdx.x * TILE_M * N_CLASSES);
        #pragma unroll
        for (int i = tid; i < TILE_M * N_CLASSES / 4; i += THREADS)
            og[i] = osv[i];
    }
}

extern "C" void kernel_launch(void* const* d_in, const int* in_sizes, int n_in,
                              void* d_out, int out_size)
{
    const float* x      = (const float*)d_in[0];
    const float* params = (const float*)d_in[1];
    float* out          = (float*)d_out;

    int batch = in_sizes[0] / INPUT_DIM;

    cudaFuncSetAttribute(sdt_mma_kernel,
                         cudaFuncAttributeMaxDynamicSharedMemorySize,
                         SMEM_TOTAL);

    sdt_setup_kernel<<<SETUP_BLOCKS, 128>>>(params);

    int grid = (batch + TILE_M - 1) / TILE_M;
    sdt_mma_kernel<<<grid, THREADS, SMEM_TOTAL>>>(x, out, batch);
}

// round 16
// speedup vs baseline: 1.3754x; 1.2065x over previous
#include <cuda_runtime.h>
#include <cuda_bf16.h>
#include <cstdint>

#define N_TREES     15
#define DEPTH       3
#define INPUT_DIM   128
#define N_CLASSES   10
#define N_LEAVES    8
#define N_INTERNAL  7
#define PER_TREE    983          // 7*128 + 7 + 8*10
#define NODES       105
#define N_PAD       112          // 14 * 8
#define TILE_M      128
#define THREADS     256          // 8 warps: 4 M-groups(M=32) x 2 N-halves(N=56)
#define M_STRIDE    12           // padded leaf-class row (10 -> 12 for float4)

// ---- smem byte offsets ----
#define OFF_MTAB    0            // 15*8*12 floats = 5760 B
#define OFF_BIAS    5760         // 112 floats = 448 B
#define OFF_BHI     6272         // 112x128 bf16 swizzled = 28672 B
#define OFF_AHI     34944        // 128x128 bf16 swizzled = 32768 B
#define OFF_ALO     67712        // 32768 B (A_lo; reused for B_lo in pass 2)
#define SMEM_TOTAL  100480
// overlays after mainloop:
#define OFF_ZS      OFF_AHI      // z tile 128*116*4 = 59392 B
#define OFF_OSM     OFF_BHI      // 2*128*10 floats = 10240 B (B_hi dead)
#define Z_STRIDE    116          // 464 B/row: 16B-aligned rows

#define B_BYTES     28672        // 112 rows * 256 B
#define SETUP_BLOCKS 64

typedef unsigned long long ull;

__device__ __align__(16) unsigned char gBhi[B_BYTES];
__device__ __align__(16) unsigned char gBlo[B_BYTES];
__device__ float gBias[N_PAD];
__device__ __align__(16) float gMtab[N_TREES * N_LEAVES * M_STRIDE];

#define MMA16816(cc, a0, a1, a2, a3, b0, b1) \
    asm volatile("mma.sync.aligned.m16n8k16.row.col.f32.bf16.bf16.f32 " \
        "{%0,%1,%2,%3}, {%4,%5,%6,%7}, {%8,%9}, {%0,%1,%2,%3};" \
        : "+f"((cc)[0]), "+f"((cc)[1]), "+f"((cc)[2]), "+f"((cc)[3]) \
        : "r"(a0), "r"(a1), "r"(a2), "r"(a3), "r"(b0), "r"(b1))

#define LDSM_X4(r0, r1, r2, r3, addr) \
    asm volatile("ldmatrix.sync.aligned.m8n8.x4.shared.b16 {%0,%1,%2,%3}, [%4];" \
        : "=r"(r0), "=r"(r1), "=r"(r2), "=r"(r3) : "r"(addr))

#define LDSM_X2(r0, r1, addr) \
    asm volatile("ldmatrix.sync.aligned.m8n8.x2.shared.b16 {%0,%1}, [%2];" \
        : "=r"(r0), "=r"(r1) : "r"(addr))

#define FMA2(acc, a, b) \
    asm("fma.rn.f32x2 %0, %1, %2, %0;" : "+l"(acc) : "l"(a), "l"(b))

__device__ __forceinline__ ull pack2(float lo, float hi) {
    ull r; asm("mov.b64 %0, {%1, %2};" : "=l"(r) : "f"(lo), "f"(hi)); return r;
}

// packed fp32 pair -> bf16x2 (hi/lo split); rn rounding identical to __float2bfloat16
__device__ __forceinline__ void cvt_split(float a, float b, uint32_t& hh, uint32_t& ll) {
    uint32_t h;
    asm("cvt.rn.bf16x2.f32 %0, %1, %2;" : "=r"(h) : "f"(b), "f"(a));  // lo=a, hi=b
    float fa = __uint_as_float(h << 16);
    float fb = __uint_as_float(h & 0xffff0000u);
    float la = a - fa;
    float lb = b - fb;
    uint32_t l;
    asm("cvt.rn.bf16x2.f32 %0, %1, %2;" : "=r"(l) : "f"(lb), "f"(la));
    hh = h; ll = l;
}

// swizzled byte offset inside a [rows][128 bf16] tile
__device__ __host__ __forceinline__ uint32_t swz(int row, int chunk, int inb) {
    return (uint32_t)(row * 256 + (((chunk) ^ (row & 7)) << 4) + inb);
}

__device__ __forceinline__ uint32_t smem_u32(const void* p) {
    uint32_t a;
    asm("{ .reg .u64 t; cvta.to.shared.u64 t, %1; cvt.u32.u64 %0, t; }"
        : "=r"(a) : "l"(p));
    return a;
}

// ===================== setup kernel: convert W once (parallel grid) =====================
__global__ void sdt_setup_kernel(const float* __restrict__ params)
{
    const int tid = threadIdx.x;
    const int gidx = blockIdx.x * blockDim.x + tid;
    const int gstride = gridDim.x * blockDim.x;

    for (int idx = gidx; idx < N_PAD * INPUT_DIM; idx += gstride) {
        int row = idx >> 7;
        int col = idx & 127;
        float v = 0.f;
        if (row < NODES) {
            int t = row / N_INTERNAL;
            int n = row - t * N_INTERNAL;
            v = params[t * PER_TREE + n * INPUT_DIM + col];
        }
        __nv_bfloat16 h = __float2bfloat16(v);
        __nv_bfloat16 l = __float2bfloat16(v - __bfloat162float(h));
        uint32_t o = swz(row, col >> 3, (col & 7) << 1);
        *reinterpret_cast<__nv_bfloat16*>(gBhi + o) = h;
        *reinterpret_cast<__nv_bfloat16*>(gBlo + o) = l;
    }

    if (blockIdx.x == 0) {
        if (tid < N_PAD) {
            float v = 0.f;
            if (tid < NODES) {
                int t = tid / N_INTERNAL;
                int n = tid - t * N_INTERNAL;
                v = params[t * PER_TREE + N_INTERNAL * INPUT_DIM + n];
            }
            gBias[tid] = v;
        }
        if (tid < N_TREES * N_LEAVES) {
            int t = tid / N_LEAVES;
            int l = tid - t * N_LEAVES;
            const float* twl = params + N_TREES * PER_TREE;
            float mx = twl[0];
            #pragma unroll
            for (int i = 1; i < N_TREES; ++i) mx = fmaxf(mx, twl[i]);
            float s = 0.f;
            #pragma unroll
            for (int i = 0; i < N_TREES; ++i) s += __expf(twl[i] - mx);
            float tw = __expf(twl[t] - mx) / s;

            const float* ll = params + t * PER_TREE + N_INTERNAL * INPUT_DIM + N_INTERNAL
                            + l * N_CLASSES;
            float m2 = ll[0];
            #pragma unroll
            for (int c = 1; c < N_CLASSES; ++c) m2 = fmaxf(m2, ll[c]);
            float e[N_CLASSES];
            float s2 = 0.f;
            #pragma unroll
            for (int c = 0; c < N_CLASSES; ++c) { e[c] = __expf(ll[c] - m2); s2 += e[c]; }
            float inv = tw / s2;
            #pragma unroll
            for (int c = 0; c < N_CLASSES; ++c)
                gMtab[(t * N_LEAVES + l) * M_STRIDE + c] = e[c] * inv;
            gMtab[(t * N_LEAVES + l) * M_STRIDE + 10] = 0.f;
            gMtab[(t * N_LEAVES + l) * M_STRIDE + 11] = 0.f;
        }
    }
}

// ---- tree epilogue over NT trees for one row; z/bias/M pre-offset ----
// fast sigmoid (__fdividef) + recursive leaf-reach products
template<int NT>
__device__ __forceinline__ void tree_epi2(const float* __restrict__ zv,
                                          const float* __restrict__ bias,
                                          const float* __restrict__ Msm0,
                                          ull* __restrict__ acc2)
{
    #pragma unroll
    for (int k = 0; k < 5; ++k) acc2[k] = 0ull;

    #pragma unroll
    for (int t = 0; t < NT; ++t) {
        float p_[N_INTERNAL], q_[N_INTERNAL];
        #pragma unroll
        for (int n = 0; n < N_INTERNAL; ++n) {
            float zz = zv[t * N_INTERNAL + n] + bias[t * N_INTERNAL + n];
            float e  = __expf(-zz);
            float pp = __fdividef(1.f, 1.f + e);  // sigmoid(z)  -> right
            p_[n] = pp;
            q_[n] = e * pp;                        // sigmoid(-z) -> left
        }
        // recursive reach products (same multiplications as per-leaf paths)
        float r3 = q_[0] * q_[1];   // reach node3
        float r4 = q_[0] * p_[1];   // node4
        float r5 = p_[0] * q_[2];   // node5
        float r6 = p_[0] * p_[2];   // node6
        float tp[N_LEAVES];
        tp[0] = r3 * q_[3];
        tp[1] = r3 * p_[3];
        tp[2] = r4 * q_[4];
        tp[3] = r4 * p_[4];
        tp[4] = r5 * q_[5];
        tp[5] = r5 * p_[5];
        tp[6] = r6 * q_[6];
        tp[7] = r6 * p_[6];

        #pragma unroll
        for (int l = 0; l < N_LEAVES; ++l) {
            const ulonglong2* Mv = reinterpret_cast<const ulonglong2*>(
                Msm0 + (t * N_LEAVES + l) * M_STRIDE);
            ulonglong2 m01 = Mv[0];   // classes 0-3
            ulonglong2 m23 = Mv[1];   // classes 4-7
            ull m4 = *reinterpret_cast<const ull*>(
                Msm0 + (t * N_LEAVES + l) * M_STRIDE + 8);  // classes 8-9
            ull ww = pack2(tp[l], tp[l]);
            FMA2(acc2[0], ww, m01.x);
            FMA2(acc2[1], ww, m01.y);
            FMA2(acc2[2], ww, m23.x);
            FMA2(acc2[3], ww, m23.y);
            FMA2(acc2[4], ww, m4);
        }
    }
}

// ===================== main kernel =====================
__global__ __launch_bounds__(THREADS, 2)
void sdt_mma_kernel(const float* __restrict__ x,
                    float* __restrict__ out,
                    int batch)
{
    extern __shared__ char smem[];
    const uint32_t sb = smem_u32(smem);
    const int tid  = threadIdx.x;
    const int lane = tid & 31;
    const int w    = tid >> 5;         // 0..7
    const int mgrp = w >> 1;           // 0..3: rows mgrp*32 .. +31
    const int nh   = w & 1;            // 0/1:  cols nh*56 .. +55

    // ---- copy precomputed B_hi, Mtab, bias into smem ----
    {
        const uint4* src = reinterpret_cast<const uint4*>(gBhi);
        uint4* dst = reinterpret_cast<uint4*>(smem + OFF_BHI);
        #pragma unroll
        for (int i = 0; i < B_BYTES / 16 / THREADS; ++i)
            dst[tid + i * THREADS] = src[tid + i * THREADS];

        float* msm = reinterpret_cast<float*>(smem + OFF_MTAB);
        for (int i = tid; i < N_TREES * N_LEAVES * M_STRIDE; i += THREADS)
            msm[i] = gMtab[i];
        float* bsm = reinterpret_cast<float*>(smem + OFF_BIAS);
        if (tid < N_PAD) bsm[tid] = gBias[tid];
    }

    // ---- stage A: x tile -> bf16 hi/lo, swizzled; 8 cols/thread -> STS.128 ----
    {
        const float4* xv = reinterpret_cast<const float4*>(x)
                         + (size_t)blockIdx.x * TILE_M * (INPUT_DIM / 4);
        #pragma unroll
        for (int it = 0; it < TILE_M * (INPUT_DIM / 8) / THREADS; ++it) {
            int idx = tid + it * THREADS;      // 32B-chunk index
            int r  = idx >> 4;
            int c8 = idx & 15;                 // chunk (8 cols) within row
            float4 v0 = xv[r * 32 + c8 * 2];
            float4 v1 = xv[r * 32 + c8 * 2 + 1];
            uint4 hh, llv;
            cvt_split(v0.x, v0.y, hh.x, llv.x);
            cvt_split(v0.z, v0.w, hh.y, llv.y);
            cvt_split(v1.x, v1.y, hh.z, llv.z);
            cvt_split(v1.z, v1.w, hh.w, llv.w);
            uint32_t base = swz(r, c8, 0);     // 16B aligned
            *reinterpret_cast<uint4*>(smem + OFF_AHI + base) = hh;
            *reinterpret_cast<uint4*>(smem + OFF_ALO + base) = llv;
        }
    }
    __syncthreads();

    // ================= 3-pass bf16-split HMMA mainloop (R12/R14 exact) =================
    const int arow_in16 = ((lane >> 3) & 1) * 8 + (lane & 7);
    const int apar      = lane >> 4;
    const int nbase      = nh * 56;
    const int brow_local = ((lane >> 4) & 1) * 8 + (lane & 7);
    const int bpar       = (lane >> 3) & 1;
    const int brow2      = nbase + 48 + (lane & 7);
    const int bpar2      = (lane >> 3) & 1;

    float cc[2][7][4];
    #pragma unroll
    for (int mt = 0; mt < 2; ++mt)
        #pragma unroll
        for (int nt = 0; nt < 7; ++nt)
            #pragma unroll
            for (int i = 0; i < 4; ++i) cc[mt][nt][i] = 0.f;

    const uint32_t sBHI = sb + OFF_BHI;
    const uint32_t sAHI = sb + OFF_AHI;
    const uint32_t sALO = sb + OFF_ALO;

    #pragma unroll 1
    for (int pass = 0; pass < 3; ++pass) {
        const uint32_t Ab = (pass == 1) ? sALO : sAHI;   // Ah, Al, Ah
        const uint32_t Bb = (pass == 2) ? sALO : sBHI;   // Bh, Bh, Bl(in ALO)
        #pragma unroll
        for (int ks = 0; ks < 8; ++ks) {
            const int ch  = ks * 2;
            const int ach = ch + apar;
            uint32_t a[2][4];
            #pragma unroll
            for (int mt = 0; mt < 2; ++mt) {
                int arow = mgrp * 32 + mt * 16 + arow_in16;
                LDSM_X4(a[mt][0], a[mt][1], a[mt][2], a[mt][3],
                        Ab + arow * 256 + ((ach ^ (arow & 7)) << 4));
            }
            #pragma unroll
            for (int j = 0; j < 3; ++j) {
                int brow = nbase + j * 16 + brow_local;
                int bch  = ch + bpar;
                uint32_t b0A, b1A, b0B, b1B;
                LDSM_X4(b0A, b1A, b0B, b1B,
                        Bb + brow * 256 + ((bch ^ (brow & 7)) << 4));
                MMA16816(cc[0][2 * j],     a[0][0], a[0][1], a[0][2], a[0][3], b0A, b1A);
                MMA16816(cc[0][2 * j + 1], a[0][0], a[0][1], a[0][2], a[0][3], b0B, b1B);
                MMA16816(cc[1][2 * j],     a[1][0], a[1][1], a[1][2], a[1][3], b0A, b1A);
                MMA16816(cc[1][2 * j + 1], a[1][0], a[1][1], a[1][2], a[1][3], b0B, b1B);
            }
            {
                uint32_t b0, b1;
                int bch = ch + bpar2;
                LDSM_X2(b0, b1, Bb + brow2 * 256 + ((bch ^ (brow2 & 7)) << 4));
                MMA16816(cc[0][6], a[0][0], a[0][1], a[0][2], a[0][3], b0, b1);
                MMA16816(cc[1][6], a[1][0], a[1][1], a[1][2], a[1][3], b0, b1);
            }
        }
        if (pass == 1) {
            // A_lo consumed; overwrite its region with B_lo for pass 2
            __syncthreads();
            const uint4* src = reinterpret_cast<const uint4*>(gBlo);
            uint4* dst = reinterpret_cast<uint4*>(smem + OFF_ALO);
            #pragma unroll
            for (int i = 0; i < B_BYTES / 16 / THREADS; ++i)
                dst[tid + i * THREADS] = src[tid + i * THREADS];
            __syncthreads();
        }
    }

    // ---- scatter accumulators to z tile (64-bit packed stores) ----
    __syncthreads();
    float* zsm = reinterpret_cast<float*>(smem + OFF_ZS);
    {
        const int rsub  = lane >> 2;
        const int cbase = nbase + ((lane & 3) << 1);
        #pragma unroll
        for (int mt = 0; mt < 2; ++mt) {
            int row = mgrp * 32 + mt * 16 + rsub;
            #pragma unroll
            for (int nt = 0; nt < 7; ++nt) {
                int col = nt * 8 + cbase;   // even -> 8B aligned
                *reinterpret_cast<ull*>(&zsm[row * Z_STRIDE + col]) =
                    pack2(cc[mt][nt][0], cc[mt][nt][1]);
                *reinterpret_cast<ull*>(&zsm[(row + 8) * Z_STRIDE + col]) =
                    pack2(cc[mt][nt][2], cc[mt][nt][3]);
            }
        }
    }
    __syncthreads();

    // ---- tree epilogue: all 256 threads; row = tid&127, tree-half = tid>>7 ----
    {
        const float* Msm = reinterpret_cast<const float*>(smem + OFF_MTAB);
        const float* bsm = reinterpret_cast<const float*>(smem + OFF_BIAS);
        float* osm = reinterpret_cast<float*>(smem + OFF_OSM);  // [2][128][10]

        const int r    = tid & 127;
        const int half = tid >> 7;
        const float* zrow = zsm + r * Z_STRIDE;

        float zv[56];
        ull acc2[5];
        if (half == 0) {
            #pragma unroll
            for (int i = 0; i < 14; ++i) {
                float4 v = reinterpret_cast<const float4*>(zrow)[i];
                zv[4 * i + 0] = v.x; zv[4 * i + 1] = v.y;
                zv[4 * i + 2] = v.z; zv[4 * i + 3] = v.w;
            }
            tree_epi2<8>(zv, bsm, Msm, acc2);
        } else {
            #pragma unroll
            for (int i = 0; i < 12; ++i) {
                float4 v = reinterpret_cast<const float4*>(zrow + 56)[i];
                zv[4 * i + 0] = v.x; zv[4 * i + 1] = v.y;
                zv[4 * i + 2] = v.z; zv[4 * i + 3] = v.w;
            }
            zv[48] = zrow[104];
            tree_epi2<7>(zv, bsm + 56, Msm + 8 * N_LEAVES * M_STRIDE, acc2);
        }

        ull* od = reinterpret_cast<ull*>(osm + (half * TILE_M + r) * N_CLASSES);
        #pragma unroll
        for (int k = 0; k < 5; ++k) od[k] = acc2[k];
    }
    __syncthreads();

    // ---- sum halves, then coalesced store ----
    {
        float* osm = reinterpret_cast<float*>(smem + OFF_OSM);
        if (tid < TILE_M) {
            #pragma unroll
            for (int c = 0; c < N_CLASSES; ++c)
                osm[tid * N_CLASSES + c] += osm[(TILE_M + tid) * N_CLASSES + c];
        }
        __syncthreads();
        const uint4* osv = reinterpret_cast<const uint4*>(osm);
        uint4* og = reinterpret_cast<uint4*>(out + (size_t)blockIdx.x * TILE_M * N_CLASSES);
        #pragma unroll
        for (int i = tid; i < TILE_M * N_CLASSES / 4; i += THREADS)
            og[i] = osv[i];
    }
}

extern "C" void kernel_launch(void* const* d_in, const int* in_sizes, int n_in,
                              void* d_out, int out_size)
{
    const float* x      = (const float*)d_in[0];
    const float* params = (const float*)d_in[1];
    float* out          = (float*)d_out;

    int batch = in_sizes[0] / INPUT_DIM;

    cudaFuncSetAttribute(sdt_mma_kernel,
                         cudaFuncAttributeMaxDynamicSharedMemorySize,
                         SMEM_TOTAL);

    sdt_setup_kernel<<<SETUP_BLOCKS, 128>>>(params);

    int grid = (batch + TILE_M - 1) / TILE_M;
    sdt_mma_kernel<<<grid, THREADS, SMEM_TOTAL>>>(x, out, batch);
}

// round 17
// speedup vs baseline: 1.4507x; 1.0547x over previous
#include <cuda_runtime.h>
#include <cuda_bf16.h>
#include <cstdint>

#define N_TREES     15
#define DEPTH       3
#define INPUT_DIM   128
#define N_CLASSES   10
#define N_LEAVES    8
#define N_INTERNAL  7
#define PER_TREE    983          // 7*128 + 7 + 8*10
#define NODES       105
#define N_PAD       112          // 14 * 8
#define TILE_M      128
#define THREADS     256          // 8 warps: 4 M-groups(M=32) x 2 N-halves(N=56)
#define M_STRIDE    12           // padded leaf-class row (10 -> 12 for float4)

// ---- smem byte offsets ----
#define OFF_MTAB    0            // 15*8*12 floats = 5760 B
#define OFF_BIAS    5760         // 112 floats = 448 B
#define OFF_BHI     6272         // 112x128 bf16 swizzled = 28672 B
#define OFF_AHI     34944        // 128x128 bf16 swizzled = 32768 B
#define OFF_ALO     67712        // 32768 B (A_lo; reused for B_lo in pass 2)
#define SMEM_TOTAL  100480
// overlays after mainloop:
#define OFF_ZS      OFF_AHI      // z tile 128*116*4 = 59392 B
#define OFF_OSM     OFF_BHI      // 4*128*10 floats = 20480 B (B_hi dead)
#define Z_STRIDE    116          // 464 B/row: 16B-aligned rows

#define B_BYTES     28672        // 112 rows * 256 B
#define SETUP_BLOCKS 64

typedef unsigned long long ull;

__device__ __align__(16) unsigned char gBhi[B_BYTES];
__device__ __align__(16) unsigned char gBlo[B_BYTES];
__device__ float gBias[N_PAD];
__device__ __align__(16) float gMtab[N_TREES * N_LEAVES * M_STRIDE];

#define MMA16816(cc, a0, a1, a2, a3, b0, b1) \
    asm volatile("mma.sync.aligned.m16n8k16.row.col.f32.bf16.bf16.f32 " \
        "{%0,%1,%2,%3}, {%4,%5,%6,%7}, {%8,%9}, {%0,%1,%2,%3};" \
        : "+f"((cc)[0]), "+f"((cc)[1]), "+f"((cc)[2]), "+f"((cc)[3]) \
        : "r"(a0), "r"(a1), "r"(a2), "r"(a3), "r"(b0), "r"(b1))

#define LDSM_X4(r0, r1, r2, r3, addr) \
    asm volatile("ldmatrix.sync.aligned.m8n8.x4.shared.b16 {%0,%1,%2,%3}, [%4];" \
        : "=r"(r0), "=r"(r1), "=r"(r2), "=r"(r3) : "r"(addr))

#define LDSM_X2(r0, r1, addr) \
    asm volatile("ldmatrix.sync.aligned.m8n8.x2.shared.b16 {%0,%1}, [%2];" \
        : "=r"(r0), "=r"(r1) : "r"(addr))

#define FMA2(acc, a, b) \
    asm("fma.rn.f32x2 %0, %1, %2, %0;" : "+l"(acc) : "l"(a), "l"(b))

#define ADD2(acc, a) \
    asm("add.rn.f32x2 %0, %0, %1;" : "+l"(acc) : "l"(a))

#define CP_ASYNC16(dst, src) \
    asm volatile("cp.async.cg.shared.global [%0], [%1], 16;" \
        :: "r"(dst), "l"(src) : "memory")
#define CP_COMMIT()  asm volatile("cp.async.commit_group;" ::: "memory")
#define CP_WAIT0()   asm volatile("cp.async.wait_group 0;" ::: "memory")

__device__ __forceinline__ ull pack2(float lo, float hi) {
    ull r; asm("mov.b64 %0, {%1, %2};" : "=l"(r) : "f"(lo), "f"(hi)); return r;
}

// packed fp32 pair -> bf16x2 (hi/lo split); rn rounding identical to __float2bfloat16
__device__ __forceinline__ void cvt_split(float a, float b, uint32_t& hh, uint32_t& ll) {
    uint32_t h;
    asm("cvt.rn.bf16x2.f32 %0, %1, %2;" : "=r"(h) : "f"(b), "f"(a));  // lo=a, hi=b
    float fa = __uint_as_float(h << 16);
    float fb = __uint_as_float(h & 0xffff0000u);
    float la = a - fa;
    float lb = b - fb;
    uint32_t l;
    asm("cvt.rn.bf16x2.f32 %0, %1, %2;" : "=r"(l) : "f"(lb), "f"(la));
    hh = h; ll = l;
}

// swizzled byte offset inside a [rows][128 bf16] tile
__device__ __host__ __forceinline__ uint32_t swz(int row, int chunk, int inb) {
    return (uint32_t)(row * 256 + (((chunk) ^ (row & 7)) << 4) + inb);
}

__device__ __forceinline__ uint32_t smem_u32(const void* p) {
    uint32_t a;
    asm("{ .reg .u64 t; cvta.to.shared.u64 t, %1; cvt.u32.u64 %0, t; }"
        : "=r"(a) : "l"(p));
    return a;
}

// ===================== setup kernel: convert W once (parallel grid) =====================
__global__ void sdt_setup_kernel(const float* __restrict__ params)
{
    const int tid = threadIdx.x;
    const int gidx = blockIdx.x * blockDim.x + tid;
    const int gstride = gridDim.x * blockDim.x;

    for (int idx = gidx; idx < N_PAD * INPUT_DIM; idx += gstride) {
        int row = idx >> 7;
        int col = idx & 127;
        float v = 0.f;
        if (row < NODES) {
            int t = row / N_INTERNAL;
            int n = row - t * N_INTERNAL;
            v = params[t * PER_TREE + n * INPUT_DIM + col];
        }
        __nv_bfloat16 h = __float2bfloat16(v);
        __nv_bfloat16 l = __float2bfloat16(v - __bfloat162float(h));
        uint32_t o = swz(row, col >> 3, (col & 7) << 1);
        *reinterpret_cast<__nv_bfloat16*>(gBhi + o) = h;
        *reinterpret_cast<__nv_bfloat16*>(gBlo + o) = l;
    }

    if (blockIdx.x == 0) {
        if (tid < N_PAD) {
            float v = 0.f;
            if (tid < NODES) {
                int t = tid / N_INTERNAL;
                int n = tid - t * N_INTERNAL;
                v = params[t * PER_TREE + N_INTERNAL * INPUT_DIM + n];
            }
            gBias[tid] = v;
        }
        if (tid < N_TREES * N_LEAVES) {
            int t = tid / N_LEAVES;
            int l = tid - t * N_LEAVES;
            const float* twl = params + N_TREES * PER_TREE;
            float mx = twl[0];
            #pragma unroll
            for (int i = 1; i < N_TREES; ++i) mx = fmaxf(mx, twl[i]);
            float s = 0.f;
            #pragma unroll
            for (int i = 0; i < N_TREES; ++i) s += __expf(twl[i] - mx);
            float tw = __expf(twl[t] - mx) / s;

            const float* ll = params + t * PER_TREE + N_INTERNAL * INPUT_DIM + N_INTERNAL
                            + l * N_CLASSES;
            float m2 = ll[0];
            #pragma unroll
            for (int c = 1; c < N_CLASSES; ++c) m2 = fmaxf(m2, ll[c]);
            float e[N_CLASSES];
            float s2 = 0.f;
            #pragma unroll
            for (int c = 0; c < N_CLASSES; ++c) { e[c] = __expf(ll[c] - m2); s2 += e[c]; }
            float inv = tw / s2;
            #pragma unroll
            for (int c = 0; c < N_CLASSES; ++c)
                gMtab[(t * N_LEAVES + l) * M_STRIDE + c] = e[c] * inv;
            gMtab[(t * N_LEAVES + l) * M_STRIDE + 10] = 0.f;
            gMtab[(t * N_LEAVES + l) * M_STRIDE + 11] = 0.f;
        }
    }
}

// ---- tree epilogue: NT trees, TWO rows at once (Mtab loads shared) ----
template<int NT>
__device__ __forceinline__ void tree_epi4(const float* __restrict__ zv0,
                                          const float* __restrict__ zv1,
                                          const float* __restrict__ bias,
                                          const float* __restrict__ Msm0,
                                          ull* __restrict__ acc0,
                                          ull* __restrict__ acc1)
{
    #pragma unroll
    for (int k = 0; k < 5; ++k) { acc0[k] = 0ull; acc1[k] = 0ull; }

    #pragma unroll
    for (int t = 0; t < NT; ++t) {
        float p0[N_INTERNAL], q0[N_INTERNAL], p1[N_INTERNAL], q1[N_INTERNAL];
        #pragma unroll
        for (int n = 0; n < N_INTERNAL; ++n) {
            float b  = bias[t * N_INTERNAL + n];
            float e0 = __expf(-(zv0[t * N_INTERNAL + n] + b));
            float s0 = __fdividef(1.f, 1.f + e0);
            p0[n] = s0; q0[n] = e0 * s0;
            float e1 = __expf(-(zv1[t * N_INTERNAL + n] + b));
            float s1 = __fdividef(1.f, 1.f + e1);
            p1[n] = s1; q1[n] = e1 * s1;
        }
        float tpa[N_LEAVES], tpb[N_LEAVES];
        {
            float r3 = q0[0] * q0[1], r4 = q0[0] * p0[1];
            float r5 = p0[0] * q0[2], r6 = p0[0] * p0[2];
            tpa[0] = r3 * q0[3]; tpa[1] = r3 * p0[3];
            tpa[2] = r4 * q0[4]; tpa[3] = r4 * p0[4];
            tpa[4] = r5 * q0[5]; tpa[5] = r5 * p0[5];
            tpa[6] = r6 * q0[6]; tpa[7] = r6 * p0[6];
        }
        {
            float r3 = q1[0] * q1[1], r4 = q1[0] * p1[1];
            float r5 = p1[0] * q1[2], r6 = p1[0] * p1[2];
            tpb[0] = r3 * q1[3]; tpb[1] = r3 * p1[3];
            tpb[2] = r4 * q1[4]; tpb[3] = r4 * p1[4];
            tpb[4] = r5 * q1[5]; tpb[5] = r5 * p1[5];
            tpb[6] = r6 * q1[6]; tpb[7] = r6 * p1[6];
        }
        #pragma unroll
        for (int l = 0; l < N_LEAVES; ++l) {
            const ulonglong2* Mv = reinterpret_cast<const ulonglong2*>(
                Msm0 + (t * N_LEAVES + l) * M_STRIDE);
            ulonglong2 m01 = Mv[0];   // classes 0-3
            ulonglong2 m23 = Mv[1];   // classes 4-7
            ull m4 = *reinterpret_cast<const ull*>(
                Msm0 + (t * N_LEAVES + l) * M_STRIDE + 8);  // classes 8-9
            ull w0 = pack2(tpa[l], tpa[l]);
            ull w1 = pack2(tpb[l], tpb[l]);
            FMA2(acc0[0], w0, m01.x); FMA2(acc1[0], w1, m01.x);
            FMA2(acc0[1], w0, m01.y); FMA2(acc1[1], w1, m01.y);
            FMA2(acc0[2], w0, m23.x); FMA2(acc1[2], w1, m23.x);
            FMA2(acc0[3], w0, m23.y); FMA2(acc1[3], w1, m23.y);
            FMA2(acc0[4], w0, m4);    FMA2(acc1[4], w1, m4);
        }
    }
}

// ===================== main kernel =====================
__global__ __launch_bounds__(THREADS, 2)
void sdt_mma_kernel(const float* __restrict__ x,
                    float* __restrict__ out,
                    int batch)
{
    extern __shared__ char smem[];
    const uint32_t sb = smem_u32(smem);
    const int tid  = threadIdx.x;
    const int lane = tid & 31;
    const int w    = tid >> 5;         // 0..7
    const int mgrp = w >> 1;           // 0..3: rows mgrp*32 .. +31
    const int nh   = w & 1;            // 0/1:  cols nh*56 .. +55

    // ---- B_hi via cp.async (overlaps A staging below); Mtab/bias direct ----
    {
        #pragma unroll
        for (int i = 0; i < B_BYTES / 16 / THREADS; ++i) {
            uint32_t off = (uint32_t)(tid + i * THREADS) * 16;
            CP_ASYNC16(sb + OFF_BHI + off,
                       reinterpret_cast<const char*>(gBhi) + off);
        }
        CP_COMMIT();

        float* msm = reinterpret_cast<float*>(smem + OFF_MTAB);
        for (int i = tid; i < N_TREES * N_LEAVES * M_STRIDE; i += THREADS)
            msm[i] = gMtab[i];
        float* bsm = reinterpret_cast<float*>(smem + OFF_BIAS);
        if (tid < N_PAD) bsm[tid] = gBias[tid];
    }

    // ---- stage A: x tile -> bf16 hi/lo, swizzled; 8 cols/thread -> STS.128 ----
    {
        const float4* xv = reinterpret_cast<const float4*>(x)
                         + (size_t)blockIdx.x * TILE_M * (INPUT_DIM / 4);
        #pragma unroll
        for (int it = 0; it < TILE_M * (INPUT_DIM / 8) / THREADS; ++it) {
            int idx = tid + it * THREADS;      // 32B-chunk index
            int r  = idx >> 4;
            int c8 = idx & 15;                 // chunk (8 cols) within row
            float4 v0 = xv[r * 32 + c8 * 2];
            float4 v1 = xv[r * 32 + c8 * 2 + 1];
            uint4 hh, llv;
            cvt_split(v0.x, v0.y, hh.x, llv.x);
            cvt_split(v0.z, v0.w, hh.y, llv.y);
            cvt_split(v1.x, v1.y, hh.z, llv.z);
            cvt_split(v1.z, v1.w, hh.w, llv.w);
            uint32_t base = swz(r, c8, 0);     // 16B aligned
            *reinterpret_cast<uint4*>(smem + OFF_AHI + base) = hh;
            *reinterpret_cast<uint4*>(smem + OFF_ALO + base) = llv;
        }
    }
    CP_WAIT0();
    __syncthreads();

    // ================= 3-pass bf16-split HMMA mainloop =================
    // pass 0: Al x Bh   (A_lo dies here)
    // pass 1: Ah x Bh   (B_lo cp.async streams into A_lo region underneath)
    // pass 2: Ah x Bl
    const int arow_in16 = ((lane >> 3) & 1) * 8 + (lane & 7);
    const int apar      = lane >> 4;
    const int nbase      = nh * 56;
    const int brow_local = ((lane >> 4) & 1) * 8 + (lane & 7);
    const int bpar       = (lane >> 3) & 1;
    const int brow2      = nbase + 48 + (lane & 7);
    const int bpar2      = (lane >> 3) & 1;

    float cc[2][7][4];
    #pragma unroll
    for (int mt = 0; mt < 2; ++mt)
        #pragma unroll
        for (int nt = 0; nt < 7; ++nt)
            #pragma unroll
            for (int i = 0; i < 4; ++i) cc[mt][nt][i] = 0.f;

    const uint32_t sBHI = sb + OFF_BHI;
    const uint32_t sAHI = sb + OFF_AHI;
    const uint32_t sALO = sb + OFF_ALO;

    #pragma unroll 1
    for (int pass = 0; pass < 3; ++pass) {
        const uint32_t Ab = (pass == 0) ? sALO : sAHI;   // Al, Ah, Ah
        const uint32_t Bb = (pass == 2) ? sALO : sBHI;   // Bh, Bh, Bl(in ALO)
        #pragma unroll
        for (int ks = 0; ks < 8; ++ks) {
            const int ch  = ks * 2;
            const int ach = ch + apar;
            uint32_t a[2][4];
            #pragma unroll
            for (int mt = 0; mt < 2; ++mt) {
                int arow = mgrp * 32 + mt * 16 + arow_in16;
                LDSM_X4(a[mt][0], a[mt][1], a[mt][2], a[mt][3],
                        Ab + arow * 256 + ((ach ^ (arow & 7)) << 4));
            }
            #pragma unroll
            for (int j = 0; j < 3; ++j) {
                int brow = nbase + j * 16 + brow_local;
                int bch  = ch + bpar;
                uint32_t b0A, b1A, b0B, b1B;
                LDSM_X4(b0A, b1A, b0B, b1B,
                        Bb + brow * 256 + ((bch ^ (brow & 7)) << 4));
                MMA16816(cc[0][2 * j],     a[0][0], a[0][1], a[0][2], a[0][3], b0A, b1A);
                MMA16816(cc[0][2 * j + 1], a[0][0], a[0][1], a[0][2], a[0][3], b0B, b1B);
                MMA16816(cc[1][2 * j],     a[1][0], a[1][1], a[1][2], a[1][3], b0A, b1A);
                MMA16816(cc[1][2 * j + 1], a[1][0], a[1][1], a[1][2], a[1][3], b0B, b1B);
            }
            {
                uint32_t b0, b1;
                int bch = ch + bpar2;
                LDSM_X2(b0, b1, Bb + brow2 * 256 + ((bch ^ (brow2 & 7)) << 4));
                MMA16816(cc[0][6], a[0][0], a[0][1], a[0][2], a[0][3], b0, b1);
                MMA16816(cc[1][6], a[1][0], a[1][1], a[1][2], a[1][3], b0, b1);
            }
        }
        if (pass == 0) {
            // A_lo consumed everywhere; stream B_lo into its region async
            __syncthreads();
            #pragma unroll
            for (int i = 0; i < B_BYTES / 16 / THREADS; ++i) {
                uint32_t off = (uint32_t)(tid + i * THREADS) * 16;
                CP_ASYNC16(sb + OFF_ALO + off,
                           reinterpret_cast<const char*>(gBlo) + off);
            }
            CP_COMMIT();
        } else if (pass == 1) {
            CP_WAIT0();
            __syncthreads();
        }
    }

    // ---- scatter accumulators to z tile (64-bit packed stores) ----
    __syncthreads();
    float* zsm = reinterpret_cast<float*>(smem + OFF_ZS);
    {
        const int rsub  = lane >> 2;
        const int cbase = nbase + ((lane & 3) << 1);
        #pragma unroll
        for (int mt = 0; mt < 2; ++mt) {
            int row = mgrp * 32 + mt * 16 + rsub;
            #pragma unroll
            for (int nt = 0; nt < 7; ++nt) {
                int col = nt * 8 + cbase;   // even -> 8B aligned
                *reinterpret_cast<ull*>(&zsm[row * Z_STRIDE + col]) =
                    pack2(cc[mt][nt][0], cc[mt][nt][1]);
                *reinterpret_cast<ull*>(&zsm[(row + 8) * Z_STRIDE + col]) =
                    pack2(cc[mt][nt][2], cc[mt][nt][3]);
            }
        }
    }
    __syncthreads();

    // ---- tree epilogue: 4 tree-groups x 64 threads, 2 rows/thread ----
    {
        const float* Msm = reinterpret_cast<const float*>(smem + OFF_MTAB);
        const float* bsm = reinterpret_cast<const float*>(smem + OFF_BIAS);
        float* osm = reinterpret_cast<float*>(smem + OFF_OSM);  // [4][128][10]

        const int g  = tid >> 6;           // tree group: {0-3,4-7,8-11,12-14}
        const int rr = tid & 63;           // rows rr and rr+64
        const int cb = g * 28;             // z col base (16B aligned: 112B)

        float zv0[28], zv1[28];
        const float* zr0 = zsm + rr * Z_STRIDE + cb;
        const float* zr1 = zsm + (rr + 64) * Z_STRIDE + cb;
        #pragma unroll
        for (int i = 0; i < 7; ++i) {
            float4 a = reinterpret_cast<const float4*>(zr0)[i];
            zv0[4 * i] = a.x; zv0[4 * i + 1] = a.y; zv0[4 * i + 2] = a.z; zv0[4 * i + 3] = a.w;
            float4 b = reinterpret_cast<const float4*>(zr1)[i];
            zv1[4 * i] = b.x; zv1[4 * i + 1] = b.y; zv1[4 * i + 2] = b.z; zv1[4 * i + 3] = b.w;
        }

        ull acc0[5], acc1[5];
        if (g == 3) tree_epi4<3>(zv0, zv1, bsm + cb, Msm + 12 * N_LEAVES * M_STRIDE, acc0, acc1);
        else        tree_epi4<4>(zv0, zv1, bsm + cb, Msm + g * 4 * N_LEAVES * M_STRIDE, acc0, acc1);

        ull* o0 = reinterpret_cast<ull*>(osm + (g * TILE_M + rr) * N_CLASSES);
        ull* o1 = reinterpret_cast<ull*>(osm + (g * TILE_M + rr + 64) * N_CLASSES);
        #pragma unroll
        for (int k = 0; k < 5; ++k) { o0[k] = acc0[k]; o1[k] = acc1[k]; }
    }
    __syncthreads();

    // ---- reduce 4 partials (packed f32x2 adds), then coalesced store ----
    {
        float* osm = reinterpret_cast<float*>(smem + OFF_OSM);
        if (tid < TILE_M) {
            ull* r0 = reinterpret_cast<ull*>(osm + tid * N_CLASSES);
            #pragma unroll
            for (int k = 0; k < 5; ++k) {
                ull s = r0[k];
                ADD2(s, reinterpret_cast<const ull*>(osm + (TILE_M + tid) * N_CLASSES)[k]);
                ADD2(s, reinterpret_cast<const ull*>(osm + (2 * TILE_M + tid) * N_CLASSES)[k]);
                ADD2(s, reinterpret_cast<const ull*>(osm + (3 * TILE_M + tid) * N_CLASSES)[k]);
                r0[k] = s;
            }
        }
        __syncthreads();
        const uint4* osv = reinterpret_cast<const uint4*>(osm);
        uint4* og = reinterpret_cast<uint4*>(out + (size_t)blockIdx.x * TILE_M * N_CLASSES);
        #pragma unroll
        for (int i = tid; i < TILE_M * N_CLASSES / 4; i += THREADS)
            og[i] = osv[i];
    }
}

extern "C" void kernel_launch(void* const* d_in, const int* in_sizes, int n_in,
                              void* d_out, int out_size)
{
    const float* x      = (const float*)d_in[0];
    const float* params = (const float*)d_in[1];
    float* out          = (float*)d_out;

    int batch = in_sizes[0] / INPUT_DIM;

    cudaFuncSetAttribute(sdt_mma_kernel,
                         cudaFuncAttributeMaxDynamicSharedMemorySize,
                         SMEM_TOTAL);

    sdt_setup_kernel<<<SETUP_BLOCKS, 128>>>(params);

    int grid = (batch + TILE_M - 1) / TILE_M;
    sdt_mma_kernel<<<grid, THREADS, SMEM_TOTAL>>>(x, out, batch);
}